// round 6
// baseline (speedup 1.0000x reference)
#include <cuda_runtime.h>
#include <cuda_fp16.h>
#include <math.h>

// Problem constants
#define BT 512      // batch
#define IC 1152     // in capsules
#define DD 8        // in dim
#define OC 10       // out capsules
#define EC 16       // out dim
#define G  2        // batches per CTA
#define T  512      // threads per CTA
#define NW 16       // warps
#define NCH 9       // chunks of 128 rows
#define RPC 128     // rows per chunk

typedef unsigned long long u64;

// Reordered fp16 W: [o][c(9)][j(4)][slot(512)][8 halves]
// slot = rl*4+eg (rl row-in-chunk, eg e-quarter); j = d-pair {2j,2j+1};
// 8 halves = (d=2j: e01,e23), (d=2j+1: e01,e23)
__device__ __align__(16) __half Wh[(size_t)OC * IC * DD * EC];

__global__ void prep_kernel(const float* __restrict__ W) {
    int t = blockIdx.x * blockDim.x + threadIdx.x;   // < 184320
    int slot = t % 512;
    int r = t / 512;
    int j = r & 3; r >>= 2;
    int c = r % NCH;
    int o = r / NCH;
    int i = c * RPC + (slot >> 2);
    int eg = slot & 3;
    const float4* src = (const float4*)(W + ((size_t)o * IC + i) * 128);
    float4 a = src[(2 * j) * 4 + eg];       // d = 2j,   e = eg*4..+3
    float4 b = src[(2 * j + 1) * 4 + eg];   // d = 2j+1, e = eg*4..+3
    __half2 h[4];
    h[0] = __floats2half2_rn(a.x, a.y);
    h[1] = __floats2half2_rn(a.z, a.w);
    h[2] = __floats2half2_rn(b.x, b.y);
    h[3] = __floats2half2_rn(b.z, b.w);
    ((uint4*)Wh)[t] = *(uint4*)h;
}

// ---- packed fp32x2 helpers ----
__device__ __forceinline__ u64 pk2(float a, float b) {
    u64 r; asm("mov.b64 %0, {%1, %2};" : "=l"(r) : "f"(a), "f"(b)); return r;
}
__device__ __forceinline__ void fma2(u64& d, u64 a, u64 b) {
    asm("fma.rn.f32x2 %0, %1, %2, %3;" : "=l"(d) : "l"(a), "l"(b), "l"(d));
}
__device__ __forceinline__ float2 up2(u64 a) {
    float2 f; asm("mov.b64 {%0, %1}, %2;" : "=f"(f.x), "=f"(f.y) : "l"(a)); return f;
}

__device__ __forceinline__ void cp_async16(unsigned smem_addr, const void* gptr) {
    asm volatile("cp.async.cg.shared.global [%0], [%1], 16;\n"
                 :: "r"(smem_addr), "l"(gptr) : "memory");
}
template <int N>
__device__ __forceinline__ void cp_wait() {
    asm volatile("cp.async.wait_group %0;\n" :: "n"(N) : "memory");
}

// Shared layout (bytes):
//  wbuf  : 3 chunk buffers x 2048 uint4 = 98304
//  larr  : [2][NCH][T] floats           = 36864
//  redv  : [2][NW][16]                  = 2048
//  redz  : [2][NW]                      = 128
//  bc    : [32]                         = 128
#define WBUF_VECS 2048
#define SMEM_BYTES (3*WBUF_VECS*16 + 2*NCH*T*4 + 2*NW*16*4 + 2*NW*4 + 32*4)

__device__ __forceinline__ void issue_chunk(unsigned sbase, int buf,
                                            const uint4* WoU, int c, int tid) {
    #pragma unroll
    for (int j = 0; j < 4; ++j)
        cp_async16(sbase + (unsigned)((buf * WBUF_VECS + j * T + tid) * 16),
                   WoU + ((size_t)(c * 4 + j) * T + tid));
    asm volatile("cp.async.commit_group;\n" ::: "memory");
}

__global__ __launch_bounds__(T, 1)
void caps_main(const float* __restrict__ x, float* __restrict__ out) {
    extern __shared__ float sm[];
    uint4* wbuf4  = (uint4*)sm;                      // [3][4][T]
    float* larr_s = sm + 3 * WBUF_VECS * 4;          // [2][NCH][T]
    float* redv   = larr_s + 2 * NCH * T;            // [2][NW][16]
    float* redz   = redv + 2 * NW * 16;              // [2][NW]
    float* bc     = redz + 2 * NW;                   // [32]

    const int o   = blockIdx.y;
    const int b0  = blockIdx.x * G;
    const int tid = threadIdx.x;
    const int w    = tid >> 5;
    const int lane = tid & 31;
    const int rl   = tid >> 2;   // row within chunk (0..127)
    const int eg   = tid & 3;    // e-quarter

    const uint4* WoU = ((const uint4*)Wh) + (size_t)o * (NCH * 4 * T);
    const unsigned sbase = (unsigned)__cvta_generic_to_shared(wbuf4);

    // x row pointers (2 float4 per row per g); chunk c offset = c*RPC*2 float4
    const float4* xp0 = (const float4*)(x + ((size_t)(b0 + 0) * IC + rl) * DD);
    const float4* xp1 = (const float4*)(x + ((size_t)(b0 + 1) * IC + rl) * DD);

    // Packed priors: P2[g][c*2 + h] = f32x2 pair (e = eg*4 + 2h, +1)
    u64 P2[G][NCH * 2];
    u64 V00 = 0, V01 = 0, V10 = 0, V11 = 0;
    const u64 ONE2 = pk2(1.f, 1.f);

    // ---------------- Phase 1: cp.async 3-deep, barrier-free ----------------
    issue_chunk(sbase, 0, WoU, 0, tid);
    issue_chunk(sbase, 1, WoU, 1, tid);
    issue_chunk(sbase, 2, WoU, 2, tid);

    #pragma unroll
    for (int c = 0; c < NCH; ++c) {
        const int b = c % 3;
        // issue x loads early (latency covered by W convert work + other warps)
        float4 x0a = xp0[c * 256], x0b = xp0[c * 256 + 1];
        float4 x1a = xp1[c * 256], x1b = xp1[c * 256 + 1];

        if (c < NCH - 2)      cp_wait<2>();
        else if (c == NCH - 2) cp_wait<1>();
        else                   cp_wait<0>();

        uint4 wv[4];
        #pragma unroll
        for (int j = 0; j < 4; ++j)
            wv[j] = wbuf4[b * WBUF_VECS + j * T + tid];

        const float xg0[8] = {x0a.x, x0a.y, x0a.z, x0a.w, x0b.x, x0b.y, x0b.z, x0b.w};
        const float xg1[8] = {x1a.x, x1a.y, x1a.z, x1a.w, x1b.x, x1b.y, x1b.z, x1b.w};

        u64 A00 = 0, A01 = 0, A10 = 0, A11 = 0;  // [g][e-pair]
        #pragma unroll
        for (int j = 0; j < 4; ++j) {
            const __half2* hp = (const __half2*)&wv[j];
            float2 w0a = __half22float2(hp[0]);   // d=2j,   e01
            float2 w0b = __half22float2(hp[1]);   // d=2j,   e23
            float2 w1a = __half22float2(hp[2]);   // d=2j+1, e01
            float2 w1b = __half22float2(hp[3]);   // d=2j+1, e23
            u64 W0a = pk2(w0a.x, w0a.y), W0b = pk2(w0b.x, w0b.y);
            u64 W1a = pk2(w1a.x, w1a.y), W1b = pk2(w1b.x, w1b.y);
            u64 X0a = pk2(xg0[2*j],   xg0[2*j]);
            u64 X0b = pk2(xg0[2*j+1], xg0[2*j+1]);
            u64 X1a = pk2(xg1[2*j],   xg1[2*j]);
            u64 X1b = pk2(xg1[2*j+1], xg1[2*j+1]);
            fma2(A00, X0a, W0a); fma2(A00, X0b, W1a);
            fma2(A01, X0a, W0b); fma2(A01, X0b, W1b);
            fma2(A10, X1a, W0a); fma2(A10, X1b, W1a);
            fma2(A11, X1a, W0b); fma2(A11, X1b, W1b);
        }
        P2[0][c*2+0] = A00; P2[0][c*2+1] = A01;
        P2[1][c*2+0] = A10; P2[1][c*2+1] = A11;
        fma2(V00, A00, ONE2); fma2(V01, A01, ONE2);
        fma2(V10, A10, ONE2); fma2(V11, A11, ONE2);

        if (c + 3 < NCH) issue_chunk(sbase, b, WoU, c + 3, tid);
    }

    // ---------------- Phase 2: routing, both g at once ----------------
    // ---- iteration 0 (uniform): s = mean_i priors ----
    {
        float q[2][4];
        float2 f;
        f = up2(V00); q[0][0] = f.x; q[0][1] = f.y;
        f = up2(V01); q[0][2] = f.x; q[0][3] = f.y;
        f = up2(V10); q[1][0] = f.x; q[1][1] = f.y;
        f = up2(V11); q[1][2] = f.x; q[1][3] = f.y;
        #pragma unroll
        for (int off = 16; off >= 4; off >>= 1)
            #pragma unroll
            for (int g = 0; g < 2; ++g)
                #pragma unroll
                for (int j = 0; j < 4; ++j)
                    q[g][j] += __shfl_down_sync(0xFFFFFFFFu, q[g][j], off);
        if (lane < 4)
            #pragma unroll
            for (int g = 0; g < 2; ++g)
                #pragma unroll
                for (int j = 0; j < 4; ++j)
                    redv[(g * NW + w) * 16 + lane * 4 + j] = q[g][j];
        __syncthreads();
        if (tid < 32) {
            const int g = tid >> 4;
            float s = 0.f;
            #pragma unroll
            for (int k = 0; k < NW; ++k) s += redv[(g * NW + k) * 16 + (tid & 15)];
            s *= (1.f / (float)IC);
            float sq = s * s;
            sq += __shfl_xor_sync(0xFFFFFFFFu, sq, 1);
            sq += __shfl_xor_sync(0xFFFFFFFFu, sq, 2);
            sq += __shfl_xor_sync(0xFFFFFFFFu, sq, 4);
            sq += __shfl_xor_sync(0xFFFFFFFFu, sq, 8);
            float sc = sqrtf(sq) / (1.f + sq);
            bc[tid] = s * sc;
        }
        __syncthreads();
    }

    // ---- iterations 1,2: fused logit+exp+sum (no max; exp args << 88) ----
    #pragma unroll
    for (int iter = 1; iter <= 2; ++iter) {
        u64 OP00 = pk2(bc[0  + eg*4 + 0], bc[0  + eg*4 + 1]);
        u64 OP01 = pk2(bc[0  + eg*4 + 2], bc[0  + eg*4 + 3]);
        u64 OP10 = pk2(bc[16 + eg*4 + 0], bc[16 + eg*4 + 1]);
        u64 OP11 = pk2(bc[16 + eg*4 + 2], bc[16 + eg*4 + 3]);

        u64 S00 = 0, S01 = 0, S10 = 0, S11 = 0;
        float vz0 = 0.f, vz1 = 0.f;
        #pragma unroll
        for (int c = 0; c < NCH; ++c) {
            u64 D0 = 0, D1 = 0;
            fma2(D0, P2[0][c*2+0], OP00); fma2(D0, P2[0][c*2+1], OP01);
            fma2(D1, P2[1][c*2+0], OP10); fma2(D1, P2[1][c*2+1], OP11);
            float2 f0 = up2(D0), f1 = up2(D1);
            float dp0 = f0.x + f0.y;
            float dp1 = f1.x + f1.y;
            dp0 += __shfl_xor_sync(0xFFFFFFFFu, dp0, 1);
            dp1 += __shfl_xor_sync(0xFFFFFFFFu, dp1, 1);
            dp0 += __shfl_xor_sync(0xFFFFFFFFu, dp0, 2);
            dp1 += __shfl_xor_sync(0xFFFFFFFFu, dp1, 2);
            float l0, l1;
            if (iter == 1) {
                l0 = dp0; l1 = dp1;
                larr_s[(0 * NCH + c) * T + tid] = l0;
                larr_s[(1 * NCH + c) * T + tid] = l1;
            } else {
                l0 = larr_s[(0 * NCH + c) * T + tid] + dp0;
                l1 = larr_s[(1 * NCH + c) * T + tid] + dp1;
            }
            float p0 = __expf(l0);
            float p1 = __expf(l1);
            vz0 += p0; vz1 += p1;
            u64 PP0 = pk2(p0, p0), PP1 = pk2(p1, p1);
            fma2(S00, P2[0][c*2+0], PP0); fma2(S01, P2[0][c*2+1], PP0);
            fma2(S10, P2[1][c*2+0], PP1); fma2(S11, P2[1][c*2+1], PP1);
        }
        float s[2][4];
        float2 f;
        f = up2(S00); s[0][0] = f.x; s[0][1] = f.y;
        f = up2(S01); s[0][2] = f.x; s[0][3] = f.y;
        f = up2(S10); s[1][0] = f.x; s[1][1] = f.y;
        f = up2(S11); s[1][2] = f.x; s[1][3] = f.y;
        float vz[2] = {vz0, vz1};
        #pragma unroll
        for (int off = 16; off >= 4; off >>= 1) {
            #pragma unroll
            for (int g = 0; g < 2; ++g) {
                #pragma unroll
                for (int j = 0; j < 4; ++j)
                    s[g][j] += __shfl_down_sync(0xFFFFFFFFu, s[g][j], off);
                vz[g] += __shfl_down_sync(0xFFFFFFFFu, vz[g], off);
            }
        }
        if (lane < 4) {
            #pragma unroll
            for (int g = 0; g < 2; ++g)
                #pragma unroll
                for (int j = 0; j < 4; ++j)
                    redv[(g * NW + w) * 16 + lane * 4 + j] = s[g][j];
            if (lane == 0) { redz[0 * NW + w] = vz[0]; redz[1 * NW + w] = vz[1]; }
        }
        __syncthreads();
        if (tid < 32) {
            const int g = tid >> 4;
            float sv = 0.f, Z = 0.f;
            #pragma unroll
            for (int k = 0; k < NW; ++k) {
                sv += redv[(g * NW + k) * 16 + (tid & 15)];
                Z  += redz[g * NW + k];
            }
            sv *= (1.f / Z);
            float sq = sv * sv;
            sq += __shfl_xor_sync(0xFFFFFFFFu, sq, 1);
            sq += __shfl_xor_sync(0xFFFFFFFFu, sq, 2);
            sq += __shfl_xor_sync(0xFFFFFFFFu, sq, 4);
            sq += __shfl_xor_sync(0xFFFFFFFFu, sq, 8);
            float sc = sqrtf(sq) / (1.f + sq);
            bc[tid] = sv * sc;
        }
        __syncthreads();
    }

    // final output: out[o, b0+g, 0, 0, e]
    if (tid < 32) {
        const int g = tid >> 4;
        out[((size_t)o * BT + (b0 + g)) * EC + (tid & 15)] = bc[tid];
    }
}

extern "C" void kernel_launch(void* const* d_in, const int* in_sizes, int n_in,
                              void* d_out, int out_size) {
    const float* x = (const float*)d_in[0];   // [512,1152,8]
    const float* W = (const float*)d_in[1];   // [10,1152,8,16]
    float* out = (float*)d_out;               // [10,512,1,1,16]

    prep_kernel<<<720, 256>>>(W);

    cudaFuncSetAttribute(caps_main,
                         cudaFuncAttributeMaxDynamicSharedMemorySize, SMEM_BYTES);
    dim3 grid(BT / G, OC);
    caps_main<<<grid, T, SMEM_BYTES>>>(x, out);
}

// round 7
// speedup vs baseline: 1.1039x; 1.1039x over previous
#include <cuda_runtime.h>
#include <cuda_fp16.h>
#include <math.h>

// Problem constants
#define BT 512      // batch
#define IC 1152     // in capsules
#define DD 8        // in dim
#define OC 10       // out capsules
#define EC 16       // out dim
#define G  2        // batches per CTA
#define T  512      // threads per CTA
#define NW 16       // warps
#define NCH 9       // chunks of 128 rows
#define RPC 128     // rows per chunk

typedef unsigned long long u64;

// Reordered fp16 W: [o][c(9)][j(4)][slot(512)][8 halves]
// slot = rl*4+eg (rl row-in-chunk, eg e-quarter); j = d-pair {2j,2j+1};
// 8 halves = (d=2j: e01,e23), (d=2j+1: e01,e23)
__device__ __align__(16) __half Wh[(size_t)OC * IC * DD * EC];

__global__ void prep_kernel(const float* __restrict__ W) {
    int t = blockIdx.x * blockDim.x + threadIdx.x;   // < 184320
    int slot = t % 512;
    int r = t / 512;
    int j = r & 3; r >>= 2;
    int c = r % NCH;
    int o = r / NCH;
    int i = c * RPC + (slot >> 2);
    int eg = slot & 3;
    const float4* src = (const float4*)(W + ((size_t)o * IC + i) * 128);
    float4 a = src[(2 * j) * 4 + eg];       // d = 2j,   e = eg*4..+3
    float4 b = src[(2 * j + 1) * 4 + eg];   // d = 2j+1, e = eg*4..+3
    __half2 h[4];
    h[0] = __floats2half2_rn(a.x, a.y);
    h[1] = __floats2half2_rn(a.z, a.w);
    h[2] = __floats2half2_rn(b.x, b.y);
    h[3] = __floats2half2_rn(b.z, b.w);
    ((uint4*)Wh)[t] = *(uint4*)h;
}

// ---- packed fp32x2 helpers ----
__device__ __forceinline__ u64 pk2(float a, float b) {
    u64 r; asm("mov.b64 %0, {%1, %2};" : "=l"(r) : "f"(a), "f"(b)); return r;
}
__device__ __forceinline__ void fma2(u64& d, u64 a, u64 b) {
    asm("fma.rn.f32x2 %0, %1, %2, %3;" : "=l"(d) : "l"(a), "l"(b), "l"(d));
}
__device__ __forceinline__ float2 up2(u64 a) {
    float2 f; asm("mov.b64 {%0, %1}, %2;" : "=f"(f.x), "=f"(f.y) : "l"(a)); return f;
}

__global__ __launch_bounds__(T, 1)
void caps_main(const float* __restrict__ x, float* __restrict__ out) {
    __shared__ float redv[2][NW][16];
    __shared__ float redz[2][NW];
    __shared__ float bc[32];    // [g*16+e] current output vector

    const int o   = blockIdx.y;
    const int b0  = blockIdx.x * G;
    const int tid = threadIdx.x;
    const int w    = tid >> 5;
    const int lane = tid & 31;
    const int rl   = tid >> 2;   // row within chunk (0..127)
    const int eg   = tid & 3;    // e-quarter

    const uint4* WoU = ((const uint4*)Wh) + (size_t)o * (NCH * 4 * T) + tid;

    // x row pointers (2 float4 per row per g); chunk c offset = c*RPC*2 float4
    const float4* xp0 = (const float4*)(x + ((size_t)(b0 + 0) * IC + rl) * DD);
    const float4* xp1 = (const float4*)(x + ((size_t)(b0 + 1) * IC + rl) * DD);

    // Packed priors: P2[g][c*2 + h] = f32x2 pair (e = eg*4 + 2h, +1)
    u64 P2[G][NCH * 2];
    u64 V00 = 0, V01 = 0, V10 = 0, V11 = 0;
    const u64 ONE2 = pk2(1.f, 1.f);

    // ------------- Phase 1: W straight L2->regs, no smem, no barriers -------------
    #pragma unroll
    for (int c = 0; c < NCH; ++c) {
        uint4 wv[4];
        #pragma unroll
        for (int j = 0; j < 4; ++j)
            wv[j] = WoU[(size_t)(c * 4 + j) * T];
        float4 x0a = xp0[c * 256], x0b = xp0[c * 256 + 1];
        float4 x1a = xp1[c * 256], x1b = xp1[c * 256 + 1];

        const float xg0[8] = {x0a.x, x0a.y, x0a.z, x0a.w, x0b.x, x0b.y, x0b.z, x0b.w};
        const float xg1[8] = {x1a.x, x1a.y, x1a.z, x1a.w, x1b.x, x1b.y, x1b.z, x1b.w};

        u64 A00 = 0, A01 = 0, A10 = 0, A11 = 0;  // [g][e-pair]
        #pragma unroll
        for (int j = 0; j < 4; ++j) {
            const __half2* hp = (const __half2*)&wv[j];
            float2 w0a = __half22float2(hp[0]);   // d=2j,   e01
            float2 w0b = __half22float2(hp[1]);   // d=2j,   e23
            float2 w1a = __half22float2(hp[2]);   // d=2j+1, e01
            float2 w1b = __half22float2(hp[3]);   // d=2j+1, e23
            u64 W0a = pk2(w0a.x, w0a.y), W0b = pk2(w0b.x, w0b.y);
            u64 W1a = pk2(w1a.x, w1a.y), W1b = pk2(w1b.x, w1b.y);
            u64 X0a = pk2(xg0[2*j],   xg0[2*j]);
            u64 X0b = pk2(xg0[2*j+1], xg0[2*j+1]);
            u64 X1a = pk2(xg1[2*j],   xg1[2*j]);
            u64 X1b = pk2(xg1[2*j+1], xg1[2*j+1]);
            fma2(A00, X0a, W0a); fma2(A00, X0b, W1a);
            fma2(A01, X0a, W0b); fma2(A01, X0b, W1b);
            fma2(A10, X1a, W0a); fma2(A10, X1b, W1a);
            fma2(A11, X1a, W0b); fma2(A11, X1b, W1b);
        }
        P2[0][c*2+0] = A00; P2[0][c*2+1] = A01;
        P2[1][c*2+0] = A10; P2[1][c*2+1] = A11;
        fma2(V00, A00, ONE2); fma2(V01, A01, ONE2);
        fma2(V10, A10, ONE2); fma2(V11, A11, ONE2);
    }

    // ---------------- Phase 2: routing, both g at once ----------------
    // ---- iteration 0 (uniform): s = mean_i priors ----
    {
        float q[2][4];
        float2 f;
        f = up2(V00); q[0][0] = f.x; q[0][1] = f.y;
        f = up2(V01); q[0][2] = f.x; q[0][3] = f.y;
        f = up2(V10); q[1][0] = f.x; q[1][1] = f.y;
        f = up2(V11); q[1][2] = f.x; q[1][3] = f.y;
        #pragma unroll
        for (int off = 16; off >= 4; off >>= 1)
            #pragma unroll
            for (int g = 0; g < 2; ++g)
                #pragma unroll
                for (int j = 0; j < 4; ++j)
                    q[g][j] += __shfl_down_sync(0xFFFFFFFFu, q[g][j], off);
        if (lane < 4)
            #pragma unroll
            for (int g = 0; g < 2; ++g)
                #pragma unroll
                for (int j = 0; j < 4; ++j)
                    redv[g][w][lane * 4 + j] = q[g][j];
        __syncthreads();
        if (tid < 32) {
            const int g = tid >> 4;
            float s = 0.f;
            #pragma unroll
            for (int k = 0; k < NW; ++k) s += redv[g][k][tid & 15];
            s *= (1.f / (float)IC);
            float sq = s * s;
            sq += __shfl_xor_sync(0xFFFFFFFFu, sq, 1);
            sq += __shfl_xor_sync(0xFFFFFFFFu, sq, 2);
            sq += __shfl_xor_sync(0xFFFFFFFFu, sq, 4);
            sq += __shfl_xor_sync(0xFFFFFFFFu, sq, 8);
            float sc = sqrtf(sq) / (1.f + sq);
            bc[tid] = s * sc;
        }
        __syncthreads();
    }

    // ---- iterations 1,2: fused logit+exp+sum (no max; exp args << 88) ----
    float larr[2][NCH];
    #pragma unroll
    for (int iter = 1; iter <= 2; ++iter) {
        u64 OP00 = pk2(bc[0  + eg*4 + 0], bc[0  + eg*4 + 1]);
        u64 OP01 = pk2(bc[0  + eg*4 + 2], bc[0  + eg*4 + 3]);
        u64 OP10 = pk2(bc[16 + eg*4 + 0], bc[16 + eg*4 + 1]);
        u64 OP11 = pk2(bc[16 + eg*4 + 2], bc[16 + eg*4 + 3]);

        u64 S00 = 0, S01 = 0, S10 = 0, S11 = 0;
        float vz0 = 0.f, vz1 = 0.f;
        #pragma unroll
        for (int c = 0; c < NCH; ++c) {
            u64 D0 = 0, D1 = 0;
            fma2(D0, P2[0][c*2+0], OP00); fma2(D0, P2[0][c*2+1], OP01);
            fma2(D1, P2[1][c*2+0], OP10); fma2(D1, P2[1][c*2+1], OP11);
            float2 f0 = up2(D0), f1 = up2(D1);
            float dp0 = f0.x + f0.y;
            float dp1 = f1.x + f1.y;
            dp0 += __shfl_xor_sync(0xFFFFFFFFu, dp0, 1);
            dp1 += __shfl_xor_sync(0xFFFFFFFFu, dp1, 1);
            dp0 += __shfl_xor_sync(0xFFFFFFFFu, dp0, 2);
            dp1 += __shfl_xor_sync(0xFFFFFFFFu, dp1, 2);
            float l0 = (iter == 1) ? dp0 : (larr[0][c] + dp0);
            float l1 = (iter == 1) ? dp1 : (larr[1][c] + dp1);
            larr[0][c] = l0;
            larr[1][c] = l1;
            float p0 = __expf(l0);
            float p1 = __expf(l1);
            vz0 += p0; vz1 += p1;
            u64 PP0 = pk2(p0, p0), PP1 = pk2(p1, p1);
            fma2(S00, P2[0][c*2+0], PP0); fma2(S01, P2[0][c*2+1], PP0);
            fma2(S10, P2[1][c*2+0], PP1); fma2(S11, P2[1][c*2+1], PP1);
        }
        float s[2][4];
        float2 f;
        f = up2(S00); s[0][0] = f.x; s[0][1] = f.y;
        f = up2(S01); s[0][2] = f.x; s[0][3] = f.y;
        f = up2(S10); s[1][0] = f.x; s[1][1] = f.y;
        f = up2(S11); s[1][2] = f.x; s[1][3] = f.y;
        float vz[2] = {vz0, vz1};
        #pragma unroll
        for (int off = 16; off >= 4; off >>= 1) {
            #pragma unroll
            for (int g = 0; g < 2; ++g) {
                #pragma unroll
                for (int j = 0; j < 4; ++j)
                    s[g][j] += __shfl_down_sync(0xFFFFFFFFu, s[g][j], off);
                vz[g] += __shfl_down_sync(0xFFFFFFFFu, vz[g], off);
            }
        }
        if (lane < 4) {
            #pragma unroll
            for (int g = 0; g < 2; ++g)
                #pragma unroll
                for (int j = 0; j < 4; ++j)
                    redv[g][w][lane * 4 + j] = s[g][j];
            if (lane == 0) { redz[0][w] = vz[0]; redz[1][w] = vz[1]; }
        }
        __syncthreads();
        if (tid < 32) {
            const int g = tid >> 4;
            float sv = 0.f, Z = 0.f;
            #pragma unroll
            for (int k = 0; k < NW; ++k) {
                sv += redv[g][k][tid & 15];
                Z  += redz[g][k];
            }
            sv *= (1.f / Z);
            float sq = sv * sv;
            sq += __shfl_xor_sync(0xFFFFFFFFu, sq, 1);
            sq += __shfl_xor_sync(0xFFFFFFFFu, sq, 2);
            sq += __shfl_xor_sync(0xFFFFFFFFu, sq, 4);
            sq += __shfl_xor_sync(0xFFFFFFFFu, sq, 8);
            float sc = sqrtf(sq) / (1.f + sq);
            bc[tid] = sv * sc;
        }
        __syncthreads();
    }

    // final output: out[o, b0+g, 0, 0, e]
    if (tid < 32) {
        const int g = tid >> 4;
        out[((size_t)o * BT + (b0 + g)) * EC + (tid & 15)] = bc[tid];
    }
}

extern "C" void kernel_launch(void* const* d_in, const int* in_sizes, int n_in,
                              void* d_out, int out_size) {
    const float* x = (const float*)d_in[0];   // [512,1152,8]
    const float* W = (const float*)d_in[1];   // [10,1152,8,16]
    float* out = (float*)d_out;               // [10,512,1,1,16]

    prep_kernel<<<720, 256>>>(W);

    dim3 grid(BT / G, OC);
    caps_main<<<grid, T>>>(x, out);
}